// round 4
// baseline (speedup 1.0000x reference)
#include <cuda_runtime.h>
#include <math.h>

#define NN   512
#define DD   128
#define M_TOTAL 2048   // 4*512

// Scratch (device globals: no allocation allowed in kernel_launch)
__device__ float g_Pb[M_TOTAL * DD];  // (x@W1) + bias   (P formed as A1 - Q + b)
__device__ float g_Q [M_TOTAL * DD];  // x @ W2

static __device__ __forceinline__ float4 f4max(float4 a, float4 b) {
    float4 r;
    r.x = fmaxf(a.x, b.x); r.y = fmaxf(a.y, b.y);
    r.z = fmaxf(a.z, b.z); r.w = fmaxf(a.w, b.w);
    return r;
}

static __device__ __forceinline__ float4 f4fma(float s, float4 v, float4 acc) {
    acc.x = fmaf(s, v.x, acc.x);
    acc.y = fmaf(s, v.y, acc.y);
    acc.z = fmaf(s, v.z, acc.z);
    acc.w = fmaf(s, v.w, acc.w);
    return acc;
}

// ---------------------------------------------------------------------------
// Kernel 1: fused dual GEMM (no per-k FSUB).
//   A1[m,o] = sum_k x[m,k] * W[k,o]        (epilogue: Pb = A1 - Q + bias)
//   Q [m,o] = sum_k x[m,k] * W[k+128,o]
// grid 256 x 128 threads. Block = 8 rows; warp = 2 rows; lane = 4 cols.
// ---------------------------------------------------------------------------
__global__ __launch_bounds__(128)
void ec_gemm_kernel(const float* __restrict__ x,
                    const float* __restrict__ W,
                    const float* __restrict__ bias) {
    __shared__ float xs[8][DD];

    const int tid  = threadIdx.x;
    const int w    = tid >> 5;
    const int lane = tid & 31;
    const int rowBase = blockIdx.x * 8;

    // cooperative load of x tile: 8*128 = 1024 floats = 256 float4
    {
        const float4* x4 = (const float4*)(x + (size_t)rowBase * DD);
        float4*       s4 = (float4*)&xs[0][0];
        s4[tid]       = __ldg(&x4[tid]);
        s4[tid + 128] = __ldg(&x4[tid + 128]);
    }
    __syncthreads();

    const int r0 = w * 2;
    const float4 z = make_float4(0.f, 0.f, 0.f, 0.f);
    float4 a10 = z, a11 = z, aQ0 = z, aQ1 = z;  // A1 rows 0/1, Q rows 0/1

    const float4* __restrict__ W4 = (const float4*)W;

    for (int kc = 0; kc < DD; kc += 4) {
        const float4 xa = *(const float4*)&xs[r0][kc];
        const float4 xb = *(const float4*)&xs[r0 + 1][kc];

#define GSTEP(u, comp) {                                          \
        float4 w1 = __ldg(&W4[(kc + u) * 32 + lane]);             \
        float4 w2 = __ldg(&W4[(kc + u + DD) * 32 + lane]);        \
        a10 = f4fma(xa.comp, w1, a10);                            \
        aQ0 = f4fma(xa.comp, w2, aQ0);                            \
        a11 = f4fma(xb.comp, w1, a11);                            \
        aQ1 = f4fma(xb.comp, w2, aQ1); }

        GSTEP(0, x) GSTEP(1, y) GSTEP(2, z) GSTEP(3, w)
#undef GSTEP
    }

    const float4 b4 = __ldg(&((const float4*)bias)[lane]);
    const int m0 = rowBase + r0;

    float4* P4 = (float4*)g_Pb;
    float4* Q4 = (float4*)g_Q;

    // Pb = A1 - Q + bias  (== x@(W1-W2) + bias up to fp rounding)
    float4 o0, o1;
    o0.x = (a10.x - aQ0.x) + b4.x; o0.y = (a10.y - aQ0.y) + b4.y;
    o0.z = (a10.z - aQ0.z) + b4.z; o0.w = (a10.w - aQ0.w) + b4.w;
    o1.x = (a11.x - aQ1.x) + b4.x; o1.y = (a11.y - aQ1.y) + b4.y;
    o1.z = (a11.z - aQ1.z) + b4.z; o1.w = (a11.w - aQ1.w) + b4.w;

    P4[(size_t)m0 * 32 + lane]       = o0;
    P4[(size_t)(m0 + 1) * 32 + lane] = o1;
    Q4[(size_t)m0 * 32 + lane]       = aQ0;
    Q4[(size_t)(m0 + 1) * 32 + lane] = aQ1;
}

// ---------------------------------------------------------------------------
// Kernel 2: compacted-neighbor-list masked max + epilogue.
//   out[b,i,o] = max(0, Pb[b,i,o] + max_{j in nbr(b,i)} Q[b,j,o])
// Block per (b,i): 128 threads = 4 warps (grid 2048 -> ~55 warps/SM).
// Phase 1: ballot/popc compaction of the adj row into smem list (unordered).
// Phase 2: each warp scans a contiguous slice, unroll 4 (MLP>=4), FMNMX only.
// ---------------------------------------------------------------------------
__global__ __launch_bounds__(128)
void ec_maxred_kernel(const float* __restrict__ adj,
                      float* __restrict__ out) {
    __shared__ int    list[NN];
    __shared__ int    cnt;
    __shared__ float4 part[4][32];

    const int tid  = threadIdx.x;
    const int w    = tid >> 5;
    const int lane = tid & 31;
    const int bi   = blockIdx.x;        // b*NN + i
    const int b    = bi >> 9;

    if (tid == 0) cnt = 0;
    __syncthreads();

    // --- Phase 1: compact set-bit indices of adj row into list[] ---
    const float* __restrict__ arow = adj + (size_t)bi * NN;
#pragma unroll
    for (int t = 0; t < 4; ++t) {
        const int j = (w * 4 + t) * 32 + lane;
        const bool on = __ldg(&arow[j]) > 0.0f;
        const unsigned m = __ballot_sync(0xffffffffu, on);
        int base = 0;
        if (lane == 0) base = atomicAdd(&cnt, __popc(m));
        base = __shfl_sync(0xffffffffu, base, 0);
        if (on) list[base + __popc(m & ((1u << lane) - 1u))] = j;
    }
    __syncthreads();

    const int n = cnt;
    const int s = (n * w) >> 2;
    const int e = (n * (w + 1)) >> 2;

    const float4* __restrict__ Qb = ((const float4*)g_Q) + (size_t)b * NN * 32 + lane;

    const float NEG = -3.0e38f;
    float4 accA = make_float4(NEG, NEG, NEG, NEG);
    float4 accB = accA;

    int t = s;
    for (; t + 4 <= e; t += 4) {
        const int j0 = list[t], j1 = list[t + 1], j2 = list[t + 2], j3 = list[t + 3];
        const float4 q0 = __ldg(Qb + (size_t)j0 * 32);
        const float4 q1 = __ldg(Qb + (size_t)j1 * 32);
        const float4 q2 = __ldg(Qb + (size_t)j2 * 32);
        const float4 q3 = __ldg(Qb + (size_t)j3 * 32);
        accA = f4max(accA, q0);
        accB = f4max(accB, q1);
        accA = f4max(accA, q2);
        accB = f4max(accB, q3);
    }
    for (; t < e; ++t) {
        accA = f4max(accA, __ldg(Qb + (size_t)list[t] * 32));
    }
    accA = f4max(accA, accB);

    part[w][lane] = accA;
    __syncthreads();

    if (tid < 32) {
        float4 v = f4max(f4max(part[0][tid], part[1][tid]),
                         f4max(part[2][tid], part[3][tid]));
        const float4 p = __ldg(&((const float4*)g_Pb)[(size_t)bi * 32 + tid]);
        float4 r;
        r.x = fmaxf(0.f, p.x + v.x);
        r.y = fmaxf(0.f, p.y + v.y);
        r.z = fmaxf(0.f, p.z + v.z);
        r.w = fmaxf(0.f, p.w + v.w);
        ((float4*)out)[(size_t)bi * 32 + tid] = r;
    }
}

// ---------------------------------------------------------------------------
extern "C" void kernel_launch(void* const* d_in, const int* in_sizes, int n_in,
                              void* d_out, int out_size) {
    const float* x    = (const float*)d_in[0];   // (4,512,128)
    const float* adj  = (const float*)d_in[1];   // (4,512,512)
    const float* W    = (const float*)d_in[2];   // (256,128)
    const float* bias = (const float*)d_in[3];   // (128,)
    float*       out  = (float*)d_out;           // (4,512,128)

    ec_gemm_kernel<<<M_TOTAL / 8, 128>>>(x, W, bias);
    ec_maxred_kernel<<<M_TOTAL, 128>>>(adj, out);
}

// round 5
// speedup vs baseline: 1.2895x; 1.2895x over previous
#include <cuda_runtime.h>
#include <math.h>

#define NN   512
#define DD   128
#define M_TOTAL 2048   // 4*512

// Scratch (device globals: no allocation allowed in kernel_launch)
__device__ float g_Pb[M_TOTAL * DD];  // (x@W1) + bias applied in epilogue trick
__device__ float g_Q [M_TOTAL * DD];  // x @ W2

static __device__ __forceinline__ float4 f4max(float4 a, float4 b) {
    float4 r;
    r.x = fmaxf(a.x, b.x); r.y = fmaxf(a.y, b.y);
    r.z = fmaxf(a.z, b.z); r.w = fmaxf(a.w, b.w);
    return r;
}

// acc = max(acc, q + m); m in {0, -1e38}: exact when m==0.
static __device__ __forceinline__ float4 f4maxadd(float4 acc, float4 q, float m) {
    acc.x = fmaxf(acc.x, q.x + m);
    acc.y = fmaxf(acc.y, q.y + m);
    acc.z = fmaxf(acc.z, q.z + m);
    acc.w = fmaxf(acc.w, q.w + m);
    return acc;
}

static __device__ __forceinline__ float4 f4fma(float s, float4 v, float4 acc) {
    acc.x = fmaf(s, v.x, acc.x);
    acc.y = fmaf(s, v.y, acc.y);
    acc.z = fmaf(s, v.z, acc.z);
    acc.w = fmaf(s, v.w, acc.w);
    return acc;
}

// ---------------------------------------------------------------------------
// Kernel 1: fused dual GEMM (FSUB-free inner loop).
//   A1[m,o] = sum_k x[m,k] * W[k,o]        Pb = A1 - Q + bias (epilogue)
//   Q [m,o] = sum_k x[m,k] * W[k+128,o]
// grid 256 x 128 threads. Block = 8 rows; warp = 2 rows; lane = 4 cols.
// ---------------------------------------------------------------------------
__global__ __launch_bounds__(128)
void ec_gemm_kernel(const float* __restrict__ x,
                    const float* __restrict__ W,
                    const float* __restrict__ bias) {
    __shared__ float xs[8][DD];

    const int tid  = threadIdx.x;
    const int w    = tid >> 5;
    const int lane = tid & 31;
    const int rowBase = blockIdx.x * 8;

    {
        const float4* x4 = (const float4*)(x + (size_t)rowBase * DD);
        float4*       s4 = (float4*)&xs[0][0];
        s4[tid]       = __ldg(&x4[tid]);
        s4[tid + 128] = __ldg(&x4[tid + 128]);
    }
    __syncthreads();

    const int r0 = w * 2;
    const float4 z = make_float4(0.f, 0.f, 0.f, 0.f);
    float4 a10 = z, a11 = z, aQ0 = z, aQ1 = z;

    const float4* __restrict__ W4 = (const float4*)W;

    for (int kc = 0; kc < DD; kc += 4) {
        const float4 xa = *(const float4*)&xs[r0][kc];
        const float4 xb = *(const float4*)&xs[r0 + 1][kc];

#define GSTEP(u, comp) {                                          \
        float4 w1 = __ldg(&W4[(kc + u) * 32 + lane]);             \
        float4 w2 = __ldg(&W4[(kc + u + DD) * 32 + lane]);        \
        a10 = f4fma(xa.comp, w1, a10);                            \
        aQ0 = f4fma(xa.comp, w2, aQ0);                            \
        a11 = f4fma(xb.comp, w1, a11);                            \
        aQ1 = f4fma(xb.comp, w2, aQ1); }

        GSTEP(0, x) GSTEP(1, y) GSTEP(2, z) GSTEP(3, w)
#undef GSTEP
    }

    const float4 b4 = __ldg(&((const float4*)bias)[lane]);
    const int m0 = rowBase + r0;

    float4* P4 = (float4*)g_Pb;
    float4* Q4 = (float4*)g_Q;

    float4 o0, o1;
    o0.x = (a10.x - aQ0.x) + b4.x; o0.y = (a10.y - aQ0.y) + b4.y;
    o0.z = (a10.z - aQ0.z) + b4.z; o0.w = (a10.w - aQ0.w) + b4.w;
    o1.x = (a11.x - aQ1.x) + b4.x; o1.y = (a11.y - aQ1.y) + b4.y;
    o1.z = (a11.z - aQ1.z) + b4.z; o1.w = (a11.w - aQ1.w) + b4.w;

    P4[(size_t)m0 * 32 + lane]       = o0;
    P4[(size_t)(m0 + 1) * 32 + lane] = o1;
    Q4[(size_t)m0 * 32 + lane]       = aQ0;
    Q4[(size_t)(m0 + 1) * 32 + lane] = aQ1;
}

// ---------------------------------------------------------------------------
// Kernel 2: dense branchless masked max, 8-row reuse, 512 threads.
//   out[b,i,o] = max(0, Pb[b,i,o] + max_j (Q[b,j,o] + m[i,j]))
// Block = 8 i-rows x 128 o; 16 warps; warp w scans j in [w*32,(w+1)*32).
// Each Q row loaded once per block (8x i-reuse). Log-tree smem reduction.
// ---------------------------------------------------------------------------
__global__ __launch_bounds__(512, 2)
void ec_maxred_kernel(const float* __restrict__ adj,
                      float* __restrict__ out) {
    __shared__ float  adjm[8][NN];       // 16 KB additive masks {0, -1e38}
    __shared__ float4 buf[4][8][32];     // 16 KB reduction scratch

    const int tid  = threadIdx.x;
    const int w    = tid >> 5;
    const int lane = tid & 31;
    const int i0   = blockIdx.x * 8;     // first global row (b*NN + i)
    const int b    = i0 >> 9;

    // Load 8 adj rows, transform to additive masks (coalesced, no transpose)
    {
        const float4* a4 = (const float4*)(adj + (size_t)i0 * NN);
        float4*       s4 = (float4*)&adjm[0][0];
#pragma unroll
        for (int t = 0; t < 2; ++t) {
            const int idx = tid + t * 512;          // 1024 float4 total
            float4 v = __ldg(&a4[idx]);
            v.x = fmaf(v.x, 1e38f, -1e38f);
            v.y = fmaf(v.y, 1e38f, -1e38f);
            v.z = fmaf(v.z, 1e38f, -1e38f);
            v.w = fmaf(v.w, 1e38f, -1e38f);
            s4[idx] = v;
        }
    }
    __syncthreads();

    const float4* __restrict__ Qb =
        ((const float4*)g_Q) + (size_t)b * NN * 32 + lane;

    const float NEG = -3.0e38f;
    float4 acc[8];
#pragma unroll
    for (int r = 0; r < 8; ++r) acc[r] = make_float4(NEG, NEG, NEG, NEG);

    const int jbase = w * 32;
#pragma unroll 2
    for (int jc = 0; jc < 32; jc += 4) {
        const int j = jbase + jc;
        const float4 q0 = __ldg(Qb + (size_t)(j + 0) * 32);
        const float4 q1 = __ldg(Qb + (size_t)(j + 1) * 32);
        const float4 q2 = __ldg(Qb + (size_t)(j + 2) * 32);
        const float4 q3 = __ldg(Qb + (size_t)(j + 3) * 32);
#pragma unroll
        for (int r = 0; r < 8; ++r) {
            const float4 m4 = *(const float4*)&adjm[r][j];  // lane-broadcast
            acc[r] = f4maxadd(acc[r], q0, m4.x);
            acc[r] = f4maxadd(acc[r], q1, m4.y);
            acc[r] = f4maxadd(acc[r], q2, m4.z);
            acc[r] = f4maxadd(acc[r], q3, m4.w);
        }
    }

    // ---- log-tree reduction 16 -> 1 warps through 16 KB buffer ----
#define WRITE_ACC(slot) {                                         \
    _Pragma("unroll")                                             \
    for (int r = 0; r < 8; ++r) buf[slot][r][lane] = acc[r]; }
#define MERGE_ACC(slot) {                                         \
    _Pragma("unroll")                                             \
    for (int r = 0; r < 8; ++r)                                   \
        acc[r] = f4max(acc[r], buf[slot][r][lane]); }

    if (w >= 8 && w < 12) WRITE_ACC(w - 8);
    __syncthreads();
    if (w < 4) MERGE_ACC(w);
    __syncthreads();
    if (w >= 12) WRITE_ACC(w - 12);
    __syncthreads();
    if (w >= 4 && w < 8) MERGE_ACC(w - 4);
    __syncthreads();
    if (w >= 4 && w < 8) WRITE_ACC(w - 4);
    __syncthreads();
    if (w < 4) MERGE_ACC(w);
    __syncthreads();
    if (w == 2 || w == 3) WRITE_ACC(w - 2);
    __syncthreads();
    if (w < 2) MERGE_ACC(w);
    __syncthreads();
    if (w == 1) WRITE_ACC(0);
    __syncthreads();

    if (w == 0) {
        MERGE_ACC(0);
        const float4* __restrict__ P4 = (const float4*)g_Pb;
        float4* __restrict__ O4 = (float4*)out;
#pragma unroll
        for (int r = 0; r < 8; ++r) {
            const float4 p = __ldg(&P4[(size_t)(i0 + r) * 32 + lane]);
            float4 o;
            o.x = fmaxf(0.f, p.x + acc[r].x);
            o.y = fmaxf(0.f, p.y + acc[r].y);
            o.z = fmaxf(0.f, p.z + acc[r].z);
            o.w = fmaxf(0.f, p.w + acc[r].w);
            O4[(size_t)(i0 + r) * 32 + lane] = o;
        }
    }
#undef WRITE_ACC
#undef MERGE_ACC
}

// ---------------------------------------------------------------------------
extern "C" void kernel_launch(void* const* d_in, const int* in_sizes, int n_in,
                              void* d_out, int out_size) {
    const float* x    = (const float*)d_in[0];   // (4,512,128)
    const float* adj  = (const float*)d_in[1];   // (4,512,512)
    const float* W    = (const float*)d_in[2];   // (256,128)
    const float* bias = (const float*)d_in[3];   // (128,)
    float*       out  = (float*)d_out;           // (4,512,128)

    ec_gemm_kernel<<<M_TOTAL / 8, 128>>>(x, W, bias);
    ec_maxred_kernel<<<M_TOTAL / 8, 512>>>(adj, out);
}

// round 7
// speedup vs baseline: 1.2906x; 1.0008x over previous
#include <cuda_runtime.h>
#include <math.h>

#define NN   512
#define DD   128
#define M_TOTAL 2048   // 4*512

// Scratch (device globals: no allocation allowed in kernel_launch)
__device__ float g_Pb[M_TOTAL * DD];  // x@W1 - x@W2 + bias
__device__ float g_Q [M_TOTAL * DD];  // x@W2

// ---------------- packed f32x2 helpers (Blackwell; NO packed max exists) ----
typedef unsigned long long ull;

static __device__ __forceinline__ ull pk2(float a) {      // {a, a}
    ull r; unsigned ai = __float_as_uint(a);
    asm("mov.b64 %0, {%1, %1};" : "=l"(r) : "r"(ai));
    return r;
}
static __device__ __forceinline__ ull add2(ull a, ull b) {
    ull r; asm("add.rn.f32x2 %0, %1, %2;" : "=l"(r) : "l"(a), "l"(b));
    return r;
}
static __device__ __forceinline__ ull fma2(ull a, ull b, ull c) {
    ull r; asm("fma.rn.f32x2 %0, %1, %2, %3;" : "=l"(r) : "l"(a), "l"(b), "l"(c));
    return r;
}

union F4U2 { float4 f4; ull u[2]; };

static __device__ __forceinline__ float4 f4max(float4 a, float4 b) {
    float4 r;
    r.x = fmaxf(a.x, b.x); r.y = fmaxf(a.y, b.y);
    r.z = fmaxf(a.z, b.z); r.w = fmaxf(a.w, b.w);
    return r;
}

// ---------------------------------------------------------------------------
// Kernel 1: fused dual GEMM with f32x2 FMAs.
//   A1 = x@W1 ; Q = x@W2 ; Pb = A1 - Q + bias (epilogue)
// grid 512 x 128 threads. Block = 4 rows; warp = 1 row; lane = 4 cols (2 ull).
// ---------------------------------------------------------------------------
__global__ __launch_bounds__(128)
void ec_gemm_kernel(const float* __restrict__ x,
                    const float* __restrict__ W,
                    const float* __restrict__ bias) {
    __shared__ float xs[4][DD];

    const int tid  = threadIdx.x;
    const int w    = tid >> 5;
    const int lane = tid & 31;
    const int rowBase = blockIdx.x * 4;

    ((float4*)xs)[tid] = __ldg(((const float4*)(x + (size_t)rowBase * DD)) + tid);
    __syncthreads();

    ull a1[2] = {0ull, 0ull};
    ull qq[2] = {0ull, 0ull};

    const float4* __restrict__ W4 = (const float4*)W;

    for (int kc = 0; kc < DD; kc += 4) {
        F4U2 w1v[4], w2v[4];
#pragma unroll
        for (int u = 0; u < 4; ++u) {
            w1v[u].f4 = __ldg(&W4[(kc + u) * 32 + lane]);
            w2v[u].f4 = __ldg(&W4[(kc + u + DD) * 32 + lane]);
        }
        const float4 xv = *(const float4*)&xs[w][kc];
        ull xp[4];
        xp[0] = pk2(xv.x); xp[1] = pk2(xv.y); xp[2] = pk2(xv.z); xp[3] = pk2(xv.w);
#pragma unroll
        for (int u = 0; u < 4; ++u) {
            a1[0] = fma2(xp[u], w1v[u].u[0], a1[0]);
            a1[1] = fma2(xp[u], w1v[u].u[1], a1[1]);
            qq[0] = fma2(xp[u], w2v[u].u[0], qq[0]);
            qq[1] = fma2(xp[u], w2v[u].u[1], qq[1]);
        }
    }

    F4U2 A, Q;
    A.u[0] = a1[0]; A.u[1] = a1[1];
    Q.u[0] = qq[0]; Q.u[1] = qq[1];

    const float4 b4 = __ldg(&((const float4*)bias)[lane]);
    float4 P;
    P.x = (A.f4.x - Q.f4.x) + b4.x;
    P.y = (A.f4.y - Q.f4.y) + b4.y;
    P.z = (A.f4.z - Q.f4.z) + b4.z;
    P.w = (A.f4.w - Q.f4.w) + b4.w;

    const int m = rowBase + w;
    ((float4*)g_Pb)[(size_t)m * 32 + lane] = P;
    ((float4*)g_Q )[(size_t)m * 32 + lane] = Q.f4;
}

// ---------------------------------------------------------------------------
// Kernel 2: masked neighbor max, SMEM-staged Q tiles.
//   out[b,i,o] = max(0, Pb[b,i,o] + max_j (Q[b,j,o] + m[i,j]))
//   m[i,j] = 0 if adj else -1e38 (exact masking), pre-packed {m,m}.
// Payload per j per row: 2x FADD2 (fma pipe) + 4x FMNMX (alu pipe, binding).
// grid 256 x 512 threads. Block = 8 i-rows; 16 warps; warp w handles 4 j per
// 64-j chunk for all 8 rows. Q chunk staged in smem (8x i-reuse, LDS math).
// ---------------------------------------------------------------------------
__global__ __launch_bounds__(512, 2)
void ec_maxred_kernel(const float* __restrict__ adj,
                      float* __restrict__ out) {
    __shared__ float4 qt[64 * 32];      // 32 KB Q chunk; reused as reduction buf
    __shared__ ull    mbuf[8][64];      // 4 KB pre-packed masks {m,m}

    const int tid  = threadIdx.x;
    const int w    = tid >> 5;
    const int lane = tid & 31;
    const int i0   = blockIdx.x * 8;    // first global row (b*NN + i)
    const int b    = i0 >> 9;

    const float4* __restrict__ Qb4 = ((const float4*)g_Q) + (size_t)b * NN * 32;
    const float*  __restrict__ arow = adj + (size_t)i0 * NN;

    float4 acc[8];
#pragma unroll
    for (int r = 0; r < 8; ++r)
        acc[r] = make_float4(-3.0e38f, -3.0e38f, -3.0e38f, -3.0e38f);

    const int mr = tid >> 6;            // mask-prep row (0..7)
    const int mj = tid & 63;            // mask-prep j within chunk

    for (int c = 0; c < 8; ++c) {
        // stage Q chunk (64 j x 128 o = 2048 float4)
#pragma unroll
        for (int t = 0; t < 4; ++t) {
            const int idx = tid + t * 512;
            qt[idx] = __ldg(Qb4 + c * 2048 + idx);
        }
        // pre-pack masks for this chunk
        {
            const float a = __ldg(&arow[mr * NN + c * 64 + mj]);
            mbuf[mr][mj] = pk2(fmaf(a, 1e38f, -1e38f));
        }
        __syncthreads();

        const int jb = w * 4;           // this warp's 4 local j's
#pragma unroll
        for (int u = 0; u < 4; ++u) {
            const int jl = jb + u;
            F4U2 q;
            q.f4 = qt[jl * 32 + lane];
            ull m0 = mbuf[0][jl], m1 = mbuf[1][jl];
            ull m2 = mbuf[2][jl], m3 = mbuf[3][jl];
            ull m4 = mbuf[4][jl], m5 = mbuf[5][jl];
            ull m6 = mbuf[6][jl], m7 = mbuf[7][jl];

#define MROW(r, mm) {                                             \
            F4U2 t;                                               \
            t.u[0] = add2(q.u[0], mm);                            \
            t.u[1] = add2(q.u[1], mm);                            \
            acc[r].x = fmaxf(acc[r].x, t.f4.x);                   \
            acc[r].y = fmaxf(acc[r].y, t.f4.y);                   \
            acc[r].z = fmaxf(acc[r].z, t.f4.z);                   \
            acc[r].w = fmaxf(acc[r].w, t.f4.w); }

            MROW(0, m0) MROW(1, m1) MROW(2, m2) MROW(3, m3)
            MROW(4, m4) MROW(5, m5) MROW(6, m6) MROW(7, m7)
#undef MROW
        }
        __syncthreads();                // before overwriting qt/mbuf
    }

    // ---- log-tree reduction 16 -> 1 warps (reuse qt as buffer) ----
    float4 (*buf)[8][32] = (float4 (*)[8][32])qt;

#define WRITE_ACC(slot) {                                         \
    _Pragma("unroll")                                             \
    for (int r = 0; r < 8; ++r) buf[slot][r][lane] = acc[r]; }
#define MERGE_ACC(slot) {                                         \
    _Pragma("unroll")                                             \
    for (int r = 0; r < 8; ++r)                                   \
        acc[r] = f4max(acc[r], buf[slot][r][lane]); }

    if (w >= 8 && w < 12) WRITE_ACC(w - 8);
    __syncthreads();
    if (w < 4) MERGE_ACC(w);
    __syncthreads();
    if (w >= 12) WRITE_ACC(w - 12);
    __syncthreads();
    if (w >= 4 && w < 8) MERGE_ACC(w - 4);
    __syncthreads();
    if (w >= 4 && w < 8) WRITE_ACC(w - 4);
    __syncthreads();
    if (w < 4) MERGE_ACC(w);
    __syncthreads();
    if (w == 2 || w == 3) WRITE_ACC(w - 2);
    __syncthreads();
    if (w < 2) MERGE_ACC(w);
    __syncthreads();
    if (w == 1) WRITE_ACC(0);
    __syncthreads();

    if (w == 0) {
        MERGE_ACC(0);
        const float4* __restrict__ P4 = (const float4*)g_Pb;
        float4* __restrict__ O4 = (float4*)out;
#pragma unroll
        for (int r = 0; r < 8; ++r) {
            const float4 p = __ldg(&P4[(size_t)(i0 + r) * 32 + lane]);
            float4 o;
            o.x = fmaxf(0.f, p.x + acc[r].x);
            o.y = fmaxf(0.f, p.y + acc[r].y);
            o.z = fmaxf(0.f, p.z + acc[r].z);
            o.w = fmaxf(0.f, p.w + acc[r].w);
            O4[(size_t)(i0 + r) * 32 + lane] = o;
        }
    }
#undef WRITE_ACC
#undef MERGE_ACC
}

// ---------------------------------------------------------------------------
extern "C" void kernel_launch(void* const* d_in, const int* in_sizes, int n_in,
                              void* d_out, int out_size) {
    const float* x    = (const float*)d_in[0];   // (4,512,128)
    const float* adj  = (const float*)d_in[1];   // (4,512,512)
    const float* W    = (const float*)d_in[2];   // (256,128)
    const float* bias = (const float*)d_in[3];   // (128,)
    float*       out  = (float*)d_out;           // (4,512,128)

    ec_gemm_kernel<<<M_TOTAL / 4, 128>>>(x, W, bias);
    ec_maxred_kernel<<<M_TOTAL / 8, 512>>>(adj, out);
}